// round 2
// baseline (speedup 1.0000x reference)
#include <cuda_runtime.h>
#include <cuda_bf16.h>

// Problem constants: nw_out is [N=4, C=19, H=512, W=1024] float32.
#define NCH    19
#define NBAT   4
#define HH     512
#define WW     1024
#define HWP    (HH * WW)            // 524288 pixels per image
#define HWP4   (HWP / 4)            // 131072 float4 quads per image-channel
#define NPIX   (NBAT * HWP)         // 2097152
#define NQUAD  (NPIX / 4)           // 524288
#define IW_F   0.2f

// Scratch accumulators. Zeroed at module load; the finalize kernel re-zeroes
// them after consuming, so every graph replay starts from zero (no init launch).
__device__ float        g_sum[NCH] = {};
__device__ unsigned int g_cnt[NCH] = {};

__global__ __launch_bounds__(256) void msiw_main_kernel(const float4* __restrict__ x4) {
    __shared__ float        s_sum[NCH];
    __shared__ unsigned int s_cnt[NCH];
    if (threadIdx.x < NCH) {
        s_sum[threadIdx.x] = 0.0f;
        s_cnt[threadIdx.x] = 0u;
    }
    __syncthreads();

    const int stride = gridDim.x * blockDim.x;     // in quads
    for (int q = blockIdx.x * blockDim.x + threadIdx.x; q < NQUAD; q += stride) {
        const int n   = q / HWP4;                  // batch index
        const int hw4 = q - n * HWP4;              // quad position within image
        const float4* base = x4 + (size_t)n * (NCH * HWP4) + hw4;

        // Load all 19 channels as float4 (32 lanes -> 512B coalesced per
        // channel; 19 independent LDG.128 in flight per warp).
        float4 v[NCH];
#pragma unroll
        for (int c = 0; c < NCH; c++) {
            v[c] = base[(size_t)c * HWP4];
        }

        // Per-component argmax (strict > keeps first-max semantics).
        float4 m = v[0];
        int ix = 0, iy = 0, iz = 0, iw = 0;
#pragma unroll
        for (int c = 1; c < NCH; c++) {
            if (v[c].x > m.x) { m.x = v[c].x; ix = c; }
            if (v[c].y > m.y) { m.y = v[c].y; iy = c; }
            if (v[c].z > m.z) { m.z = v[c].z; iz = c; }
            if (v[c].w > m.w) { m.w = v[c].w; iw = c; }
        }

        // r = sum_c softmax^2 = s2 / s1^2 per component (max-shifted).
        float4 s1 = make_float4(0.f, 0.f, 0.f, 0.f);
        float4 s2 = make_float4(0.f, 0.f, 0.f, 0.f);
#pragma unroll
        for (int c = 0; c < NCH; c++) {
            float ex = __expf(v[c].x - m.x);
            float ey = __expf(v[c].y - m.y);
            float ez = __expf(v[c].z - m.z);
            float ew = __expf(v[c].w - m.w);
            s1.x += ex; s2.x = fmaf(ex, ex, s2.x);
            s1.y += ey; s2.y = fmaf(ey, ey, s2.y);
            s1.z += ez; s2.z = fmaf(ez, ez, s2.z);
            s1.w += ew; s2.w = fmaf(ew, ew, s2.w);
        }

        atomicAdd(&s_sum[ix], __fdividef(s2.x, s1.x * s1.x));
        atomicAdd(&s_sum[iy], __fdividef(s2.y, s1.y * s1.y));
        atomicAdd(&s_sum[iz], __fdividef(s2.z, s1.z * s1.z));
        atomicAdd(&s_sum[iw], __fdividef(s2.w, s1.w * s1.w));
        atomicAdd(&s_cnt[ix], 1u);
        atomicAdd(&s_cnt[iy], 1u);
        atomicAdd(&s_cnt[iz], 1u);
        atomicAdd(&s_cnt[iw], 1u);
    }

    __syncthreads();
    if (threadIdx.x < NCH) {
        atomicAdd(&g_sum[threadIdx.x], s_sum[threadIdx.x]);
        atomicAdd(&g_cnt[threadIdx.x], s_cnt[threadIdx.x]);
    }
}

__global__ void msiw_finalize_kernel(float* __restrict__ out) {
    // Single warp. Each thread owns one class: read, compute, then RESET the
    // global accumulators so the next graph replay starts from zero.
    int c = threadIdx.x;
    float partial = 0.0f;
    if (c < NCH) {
        float cnt   = (float)g_cnt[c];
        float scale = powf((float)NPIX, 1.0f - IW_F);        // Np^0.8
        float den   = fmaxf(powf(cnt, IW_F) * scale, 1.0f);  // max(hist^0.2 * Np^0.8, 1)
        partial = g_sum[c] / den;
        g_sum[c] = 0.0f;                                     // reset for next replay
        g_cnt[c] = 0u;
    }
#pragma unroll
    for (int o = 16; o > 0; o >>= 1)
        partial += __shfl_down_sync(0xffffffffu, partial, o);
    if (c == 0)
        out[0] = -partial / (float)(NBAT * NCH);
}

extern "C" void kernel_launch(void* const* d_in, const int* in_sizes, int n_in,
                              void* d_out, int out_size) {
    (void)in_sizes; (void)n_in; (void)out_size;
    const float4* x4 = (const float4*)d_in[0];
    float* out = (float*)d_out;

    // 1024 blocks x 256 threads: each thread handles exactly 2 float4 quads
    // (8 pixels) via the grid-stride loop.
    msiw_main_kernel<<<1024, 256>>>(x4);
    msiw_finalize_kernel<<<1, 32>>>(out);
}

// round 3
// speedup vs baseline: 1.3542x; 1.3542x over previous
#include <cuda_runtime.h>
#include <cuda_bf16.h>

// Problem constants: nw_out is [N=4, C=19, H=512, W=1024] float32.
#define NCH    19
#define NBAT   4
#define HH     512
#define WW     1024
#define HWP    (HH * WW)            // 524288 pixels per image
#define HWP2   (HWP / 2)            // 262144 float2 pairs per image-channel
#define NPIX   (NBAT * HWP)         // 2097152
#define NPAIR  (NPIX / 2)           // 1048576
#define IW_F   0.2f
#define GRID_BLOCKS 1024

// Scratch accumulators. Zeroed at module load; the fused finalize re-zeroes
// them after consuming, so every graph replay starts from zero.
__device__ float        g_sum[NCH] = {};
__device__ unsigned int g_cnt[NCH] = {};
__device__ unsigned int g_done     = 0;

__global__ __launch_bounds__(256) void msiw_kernel(const float2* __restrict__ x2,
                                                   float* __restrict__ out) {
    __shared__ float        s_sum[NCH];
    __shared__ unsigned int s_cnt[NCH];
    if (threadIdx.x < NCH) {
        s_sum[threadIdx.x] = 0.0f;
        s_cnt[threadIdx.x] = 0u;
    }
    __syncthreads();

    const int stride = gridDim.x * blockDim.x;     // in float2 pairs
    for (int q = blockIdx.x * blockDim.x + threadIdx.x; q < NPAIR; q += stride) {
        const int n   = q / HWP2;                  // batch index
        const int hw2 = q - n * HWP2;              // pair position within image
        const float2* base = x2 + (size_t)n * (NCH * HWP2) + hw2;

        // Load all 19 channels as float2 (32 lanes -> 256B coalesced per
        // channel; 19 independent LDG.64 in flight per warp).
        float2 v[NCH];
#pragma unroll
        for (int c = 0; c < NCH; c++) {
            v[c] = base[(size_t)c * HWP2];
        }

        // Per-component argmax (strict > keeps first-max semantics).
        float mx = v[0].x, my = v[0].y;
        int ix = 0, iy = 0;
#pragma unroll
        for (int c = 1; c < NCH; c++) {
            if (v[c].x > mx) { mx = v[c].x; ix = c; }
            if (v[c].y > my) { my = v[c].y; iy = c; }
        }

        // r = sum_c softmax^2 = s2 / s1^2 per component (max-shifted).
        float s1x = 0.f, s2x = 0.f, s1y = 0.f, s2y = 0.f;
#pragma unroll
        for (int c = 0; c < NCH; c++) {
            float ex = __expf(v[c].x - mx);
            float ey = __expf(v[c].y - my);
            s1x += ex; s2x = fmaf(ex, ex, s2x);
            s1y += ey; s2y = fmaf(ey, ey, s2y);
        }

        atomicAdd(&s_sum[ix], __fdividef(s2x, s1x * s1x));
        atomicAdd(&s_sum[iy], __fdividef(s2y, s1y * s1y));
        atomicAdd(&s_cnt[ix], 1u);
        atomicAdd(&s_cnt[iy], 1u);
    }

    __syncthreads();
    if (threadIdx.x < NCH) {
        atomicAdd(&g_sum[threadIdx.x], s_sum[threadIdx.x]);
        atomicAdd(&g_cnt[threadIdx.x], s_cnt[threadIdx.x]);
    }

    // ---- fused finalize: last block to finish does the 19-term reduction ----
    __threadfence();                               // make bin atomics visible
    __shared__ unsigned int s_last;
    if (threadIdx.x == 0) {
        unsigned int ticket = atomicAdd(&g_done, 1u);
        s_last = (ticket == gridDim.x - 1) ? 1u : 0u;
    }
    __syncthreads();
    if (s_last && threadIdx.x < 32) {
        int c = threadIdx.x;
        float partial = 0.0f;
        if (c < NCH) {
            float cnt   = (float)g_cnt[c];
            float scale = powf((float)NPIX, 1.0f - IW_F);        // Np^0.8
            float den   = fmaxf(powf(cnt, IW_F) * scale, 1.0f);  // max(hist^0.2*Np^0.8, 1)
            partial = g_sum[c] / den;
            g_sum[c] = 0.0f;                                     // reset for next replay
            g_cnt[c] = 0u;
        }
#pragma unroll
        for (int o = 16; o > 0; o >>= 1)
            partial += __shfl_down_sync(0xffffffffu, partial, o);
        if (c == 0) {
            out[0] = -partial / (float)(NBAT * NCH);
            g_done = 0;                                          // reset ticket
        }
    }
}

extern "C" void kernel_launch(void* const* d_in, const int* in_sizes, int n_in,
                              void* d_out, int out_size) {
    (void)in_sizes; (void)n_in; (void)out_size;
    const float2* x2 = (const float2*)d_in[0];
    float* out = (float*)d_out;

    // Single launch: 1024 blocks x 256 threads; each thread handles exactly
    // 4 float2 pairs (8 pixels) via the grid-stride loop. Finalize is fused
    // via the last-block ticket.
    msiw_kernel<<<GRID_BLOCKS, 256>>>(x2, out);
}